// round 12
// baseline (speedup 1.0000x reference)
#include <cuda_runtime.h>
#include <cstdint>

// StructureTensorEffect, B=4, C=3, H=W=1024.
// Separable: s_u = Gx*Sy, s_v = Sx*Gy, per-batch-constant stencils.
// sigma in [0.5,2.5) => JP = floor(sigma) in {0,1,2}; templated on JP.
//
// R12 = R10 (f32x2 packed vertical stencil + packed quadratics) with
// phase 2 widened to 8 px/thread: window = 16 floats = 4 LDS.128 per array
// per channel (was 6 for 4 px), bank-conflict-free via per-128B-block
// rotation swizzle (verified in R5). 256 threads, occupancy 3.

#define Wd 1024
#define Hd 1024
#define TX 128
#define TY 16
#define HX 4
#define SW (TX + 2*HX)            // 136 floats per smem row (34 float4)
#define NTH 256
#define NSTRIP (SW/4)             // 34 float4 strips
#define CHUNK 8
#define NCHUNK (TY/CHUNK)         // 2
#define NVTASK (NSTRIP*NCHUNK*3)  // 204
#define HW (Hd*Wd)
#define SMEM_FLOATS (3*TY*SW)     // per array
#define SMEM_BYTES (2*SMEM_FLOATS*4)

// ---- f32x2 packed helpers (Blackwell FFMA2 path, PTX-only) ----
__device__ __forceinline__ uint64_t pk(float lo, float hi) {
    uint64_t r;
    asm("mov.b64 %0, {%1, %2};" : "=l"(r)
        : "r"(__float_as_uint(lo)), "r"(__float_as_uint(hi)));
    return r;
}
__device__ __forceinline__ void upk(uint64_t v, float& lo, float& hi) {
    uint32_t a, b;
    asm("mov.b64 {%0, %1}, %2;" : "=r"(a), "=r"(b) : "l"(v));
    lo = __uint_as_float(a); hi = __uint_as_float(b);
}
__device__ __forceinline__ uint64_t mul2(uint64_t a, uint64_t b) {
    uint64_t r; asm("mul.rn.f32x2 %0, %1, %2;" : "=l"(r) : "l"(a), "l"(b)); return r;
}
__device__ __forceinline__ uint64_t add2(uint64_t a, uint64_t b) {
    uint64_t r; asm("add.rn.f32x2 %0, %1, %2;" : "=l"(r) : "l"(a), "l"(b)); return r;
}
__device__ __forceinline__ uint64_t fma2(uint64_t a, uint64_t b, uint64_t c) {
    uint64_t r; asm("fma.rn.f32x2 %0, %1, %2, %3;" : "=l"(r) : "l"(a), "l"(b), "l"(c)); return r;
}
#define NEG1_2 0xBF800000BF800000ULL   // (-1.f, -1.f)
#define C100_2 0x42C8000042C80000ULL   // (100.f, 100.f)

// Swizzle on float4-index within a smem row: rotate odd 128B blocks by one
// float4 (conflict-free for stride-2 window loads and strip stores; R5).
__device__ __forceinline__ int swz(int f) {
    return (f & ~7) | ((f + ((f >> 3) & 1)) & 7);
}

__device__ __forceinline__ int clampi(int v, int lo, int hi) {
    return min(max(v, lo), hi);
}

// Exact per-pixel path replicating reference clip semantics (left/top only).
__device__ __noinline__ void exact_pixel(const float* __restrict__ xb, float s,
                                         int gx, int gy,
                                         float& A, float& Bv, float& Cv) {
    const float OU[8] = {-1.f,-1.f,-1.f, 0.f, 0.f, 1.f, 1.f, 1.f};
    const float OV[8] = {-1.f, 0.f, 1.f,-1.f, 1.f,-1.f, 0.f, 1.f};
    const float KU[8] = {-0.25f,-0.5f,-0.25f, 0.f, 0.f, 0.25f, 0.5f, 0.25f};
    const float KV[8] = {-0.25f, 0.f, 0.25f,-0.5f, 0.5f,-0.25f, 0.f, 0.25f};
    float su[3] = {0.f,0.f,0.f}, sv[3] = {0.f,0.f,0.f};
    #pragma unroll
    for (int t = 0; t < 8; ++t) {
        float px = (float)gx + OU[t] * s;
        float py = (float)gy + OV[t] * s;
        float x0f = floorf(px), y0f = floorf(py);
        float fx = px - x0f, fy = py - y0f;
        int x0 = clampi((int)x0f, 0, Wd - 1);
        int x1 = min(x0 + 1, Wd - 1);
        int y0 = clampi((int)y0f, 0, Hd - 1);
        int y1 = min(y0 + 1, Hd - 1);
        float w00 = (1.f - fx) * (1.f - fy);
        float w01 = fx * (1.f - fy);
        float w10 = (1.f - fx) * fy;
        float w11 = fx * fy;
        #pragma unroll
        for (int c = 0; c < 3; ++c) {
            const float* p = xb + c * HW;
            float bil = w00 * __ldg(&p[y0 * Wd + x0]) + w01 * __ldg(&p[y0 * Wd + x1])
                      + w10 * __ldg(&p[y1 * Wd + x0]) + w11 * __ldg(&p[y1 * Wd + x1]);
            su[c] += KU[t] * bil;
            sv[c] += KV[t] * bil;
        }
    }
    A = 0.f; Bv = 0.f; Cv = 0.f;
    #pragma unroll
    for (int c = 0; c < 3; ++c) {
        float l = (c == 0) ? 100.f : 1.f;
        float a = su[c] * l, b = sv[c] * l;
        A += a * a; Bv += b * b; Cv += a * b;
    }
}

struct P2 { uint64_t lo, hi; };   // packed float4

template<int JP>
__device__ __forceinline__ void run_tile(const float* __restrict__ xb, float s,
                                         float* __restrict__ smS,
                                         float* __restrict__ smG,
                                         float* __restrict__ out,
                                         int b, int bx0, int by0, int tid) {
    const float fp  = s - (float)JP;
    const float wp0 = 0.5f * (1.f - fp);
    const float wp1 = 0.5f * fp;
    const float wm0 = wp1;
    const float wm1 = wp0;

    // ---------------- Phase 1: vertical stencil (f32x2) -> smem ----------------
    if (tid < NVTASK) {
        const int c     = tid / (NSTRIP * NCHUNK);
        const int rem   = tid - c * (NSTRIP * NCHUNK);
        const int chunk = rem / NSTRIP;
        const int strip = rem - chunk * NSTRIP;

        const float* plane = xb + c * HW;
        const int gxu  = bx0 - HX + strip * 4;            // unclamped
        const bool edge = (gxu < 0) || (gxu > Wd - 4);
        const int cx0 = clampi(gxu + 0, 0, Wd - 1);
        const int cx1 = clampi(gxu + 1, 0, Wd - 1);
        const int cx2 = clampi(gxu + 2, 0, Wd - 1);
        const int cx3 = clampi(gxu + 3, 0, Wd - 1);
        const int ybase = by0 + chunk * CHUNK;
        const int fsw   = swz(strip) * 4;                 // swizzled float offset

        const uint64_t Wm0 = pk(wm0, wm0), Wm1 = pk(wm1, wm1);
        const uint64_t Wp0 = pk(wp0, wp0), Wp1 = pk(wp1, wp1);

        auto ldrow = [&](int yy) -> P2 {
            const int yo = clampi(yy, 0, Hd - 1) * Wd;
            float4 v;
            if (!edge) {
                v = __ldg((const float4*)(plane + yo + gxu));
            } else {
                v.x = __ldg(plane + yo + cx0);
                v.y = __ldg(plane + yo + cx1);
                v.z = __ldg(plane + yo + cx2);
                v.w = __ldg(plane + yo + cx3);
            }
            P2 p; p.lo = pk(v.x, v.y); p.hi = pk(v.z, v.w);
            return p;
        };

        constexpr int WIN = 2 * JP + 3;
        P2 win[WIN];
        #pragma unroll
        for (int r = -JP - 1; r <= JP; ++r)
            win[r + JP + 1] = ldrow(ybase + r);

        float* sSrow = smS + (c * TY + chunk * CHUNK) * SW + fsw;
        float* sGrow = smG + (c * TY + chunk * CHUNK) * SW + fsw;

        #pragma unroll
        for (int j = 0; j < CHUNK; ++j) {
            win[(j + 2 * JP + 2) % WIN] = ldrow(ybase + j + JP + 1);

            P2 m0 = win[(j)              % WIN];
            P2 m1 = win[(j + 1)          % WIN];
            P2 ce = win[(j + JP + 1)     % WIN];
            P2 p0 = win[(j + 2 * JP + 1) % WIN];
            P2 p1 = win[(j + 2 * JP + 2) % WIN];

            uint64_t mpl = fma2(Wm1, m1.lo, mul2(Wm0, m0.lo));
            uint64_t mph = fma2(Wm1, m1.hi, mul2(Wm0, m0.hi));
            uint64_t ppl = fma2(Wp1, p1.lo, mul2(Wp0, p0.lo));
            uint64_t pph = fma2(Wp1, p1.hi, mul2(Wp0, p0.hi));
            uint64_t vsl = add2(ce.lo, add2(mpl, ppl));
            uint64_t vsh = add2(ce.hi, add2(mph, pph));
            uint64_t vgl = fma2(mpl, NEG1_2, ppl);       // pp - mp
            uint64_t vgh = fma2(mph, NEG1_2, pph);

            *(ulonglong2*)(sSrow + j * SW) = make_ulonglong2(vsl, vsh);
            *(ulonglong2*)(sGrow + j * SW) = make_ulonglong2(vgl, vgh);
        }
    }
    __syncthreads();

    // ---------------- Phase 2: horizontal stencil + packed quadratics ----------
    // 1 row x 8 px per thread: 16 col groups x 16 rows = 256 threads.
    const int cg = tid & 15;         // col group 0..15
    const int r  = tid >> 4;         // row 0..15
    const int xl = cg * 8;

    int fo[4];
    #pragma unroll
    for (int k = 0; k < 4; ++k) fo[k] = swz(cg * 2 + k) * 4;

    uint64_t qA[4] = {0,0,0,0}, qB[4] = {0,0,0,0}, qC[4] = {0,0,0,0};

    constexpr int dM = 3 - JP;
    constexpr int dP = 4 + JP;

    #pragma unroll
    for (int c = 0; c < 3; ++c) {
        const float* Srow = smS + (c * TY + r) * SW;
        const float* Grow = smG + (c * TY + r) * SW;
        float4 a0 = *(const float4*)(Srow + fo[0]);
        float4 a1 = *(const float4*)(Srow + fo[1]);
        float4 a2 = *(const float4*)(Srow + fo[2]);
        float4 a3 = *(const float4*)(Srow + fo[3]);
        float4 b0 = *(const float4*)(Grow + fo[0]);
        float4 b1 = *(const float4*)(Grow + fo[1]);
        float4 b2 = *(const float4*)(Grow + fo[2]);
        float4 b3 = *(const float4*)(Grow + fo[3]);
        float sw[16] = {a0.x,a0.y,a0.z,a0.w, a1.x,a1.y,a1.z,a1.w,
                        a2.x,a2.y,a2.z,a2.w, a3.x,a3.y,a3.z,a3.w};
        float gw[16] = {b0.x,b0.y,b0.z,b0.w, b1.x,b1.y,b1.z,b1.w,
                        b2.x,b2.y,b2.z,b2.w, b3.x,b3.y,b3.z,b3.w};
        float su[8], sv[8];
        #pragma unroll
        for (int i = 0; i < 8; ++i) {
            su[i] = wp0 * sw[i + dP] + wp1 * sw[i + dP + 1]
                  - wm0 * sw[i + dM] - wm1 * sw[i + dM + 1];
            sv[i] = gw[i + 4]
                  + wm0 * gw[i + dM] + wm1 * gw[i + dM + 1]
                  + wp0 * gw[i + dP] + wp1 * gw[i + dP + 1];
        }
        #pragma unroll
        for (int k = 0; k < 4; ++k) {
            uint64_t p = pk(su[2*k], su[2*k + 1]);
            uint64_t q = pk(sv[2*k], sv[2*k + 1]);
            if (c == 0) {               // lum=100 channel; others lum=1
                p = mul2(p, C100_2);
                q = mul2(q, C100_2);
            }
            qA[k] = fma2(p, p, qA[k]);
            qB[k] = fma2(q, q, qB[k]);
            qC[k] = fma2(p, q, qC[k]);
        }
    }

    // ---------------- Output ----------------
    float* out0 = out + (b * 3 + 0) * HW;
    float* out1 = out + (b * 3 + 1) * HW;
    float* out2 = out + (b * 3 + 2) * HW;
    const int gxg = bx0 + xl;
    const int gy  = by0 + r;
    const int o   = gy * Wd + gxg;

    float A[8], Bv[8], Cv[8];
    #pragma unroll
    for (int k = 0; k < 4; ++k) {
        upk(qA[k], A[2*k], A[2*k + 1]);
        upk(qB[k], Bv[2*k], Bv[2*k + 1]);
        upk(qC[k], Cv[2*k], Cv[2*k + 1]);
    }

    // Right/bottom are exact via clamped taps; fallback only left/top.
    if (gxg >= 8 && gy > JP) {
        *(float4*)(out0 + o)     = make_float4(A[0], A[1], A[2], A[3]);
        *(float4*)(out0 + o + 4) = make_float4(A[4], A[5], A[6], A[7]);
        *(float4*)(out1 + o)     = make_float4(Bv[0], Bv[1], Bv[2], Bv[3]);
        *(float4*)(out1 + o + 4) = make_float4(Bv[4], Bv[5], Bv[6], Bv[7]);
        *(float4*)(out2 + o)     = make_float4(Cv[0], Cv[1], Cv[2], Cv[3]);
        *(float4*)(out2 + o + 4) = make_float4(Cv[4], Cv[5], Cv[6], Cv[7]);
    } else {
        #pragma unroll
        for (int i = 0; i < 8; ++i) {
            int gx = gxg + i;
            float a = A[i], bq = Bv[i], cq = Cv[i];
            if (gx <= JP || gy <= JP) {
                exact_pixel(xb, s, gx, gy, a, bq, cq);
            }
            out0[o + i] = a;
            out1[o + i] = bq;
            out2[o + i] = cq;
        }
    }
}

__global__ __launch_bounds__(NTH, 3)
void st12_kernel(const float* __restrict__ x, const float* __restrict__ sigma,
                 float* __restrict__ out) {
    extern __shared__ float sm[];
    float* smS = sm;
    float* smG = sm + SMEM_FLOATS;

    const int b   = blockIdx.z;
    const int bx0 = blockIdx.x * TX;
    const int by0 = blockIdx.y * TY;
    const int tid = threadIdx.x;

    const float s = __ldg(&sigma[b]);
    const int jp = clampi((int)floorf(s), 0, 2);
    const float* xb = x + b * 3 * HW;

    if (jp == 0)      run_tile<0>(xb, s, smS, smG, out, b, bx0, by0, tid);
    else if (jp == 1) run_tile<1>(xb, s, smS, smG, out, b, bx0, by0, tid);
    else              run_tile<2>(xb, s, smS, smG, out, b, bx0, by0, tid);
}

extern "C" void kernel_launch(void* const* d_in, const int* in_sizes, int n_in,
                              void* d_out, int out_size) {
    const float* x     = (const float*)d_in[0];
    const float* sigma = (const float*)d_in[1];
    float* out = (float*)d_out;
    int B = in_sizes[1];

    static_assert(SMEM_BYTES == 52224, "smem size");
    cudaFuncSetAttribute(st12_kernel, cudaFuncAttributeMaxDynamicSharedMemorySize, SMEM_BYTES);

    dim3 grid(Wd / TX, Hd / TY, B);
    st12_kernel<<<grid, NTH, SMEM_BYTES>>>(x, sigma, out);
}